// round 1
// baseline (speedup 1.0000x reference)
#include <cuda_runtime.h>

// ---------------------------------------------------------------------------
// FourierAttention: single-head full attention over d_model.
//   Q = x@Wq^T+bq ; K = x@Wk^T+bk ; V = x@Wv^T+bv
//   S = softmax(Q K^T * 0.125) ; A = S V ; out = A@Wo^T + bo
// Shapes: B=4, S=2048, D=1024 (fp32).
// ---------------------------------------------------------------------------

#define SEQ 2048
#define DM  1024
#define NB  4
#define TOK (NB * SEQ)          // 8192

#define BM 128
#define BN 128
#define BK 8
#define TM 8
#define TN 8

// Scratch (allocation-free: __device__ globals)
__device__ float g_Q[(long long)TOK * DM];
__device__ float g_K[(long long)TOK * DM];
__device__ float g_V[(long long)TOK * DM];
__device__ float g_S[(long long)NB * SEQ * SEQ];
__device__ float g_A[(long long)TOK * DM];

// ---------------------------------------------------------------------------
// Tiled SGEMM.
//  TRANS_B = true :  C[m,n] = alpha * sum_k A[m,k] * B[n,k]  (+ bias[n])
//  TRANS_B = false:  C[m,n] = alpha * sum_k A[m,k] * B[k,n]  (+ bias[n])
// Requires M%128==0, N%128==0, K%8==0. Batched via blockIdx.z + strides.
// ---------------------------------------------------------------------------
template <bool TRANS_B, bool HAS_BIAS>
__global__ void __launch_bounds__(256, 2) gemm_kernel(
    const float* __restrict__ A, const float* __restrict__ B,
    const float* __restrict__ bias, float* __restrict__ C,
    int M, int N, int K, float alpha,
    long long strideA, long long strideB, long long strideC)
{
    __shared__ float As[BK][BM + 4];
    __shared__ float Bs[BK][BN + 4];

    const int bz = blockIdx.z;
    A += (long long)bz * strideA;
    B += (long long)bz * strideB;
    C += (long long)bz * strideC;

    const int tid  = threadIdx.x;
    const int row0 = blockIdx.y * BM;
    const int col0 = blockIdx.x * BN;
    const int tx = tid & 15;     // 0..15 -> N direction
    const int ty = tid >> 4;     // 0..15 -> M direction

    // A-tile loader: float4 along K
    const int arow = tid >> 1;          // 0..127
    const int ak   = (tid & 1) * 4;     // 0 or 4
    // B-tile loader (NN case): float4 along N
    const int bkr  = tid >> 5;          // 0..7
    const int bn4  = (tid & 31) * 4;    // 0..124

    float acc[TM][TN];
#pragma unroll
    for (int i = 0; i < TM; i++)
#pragma unroll
        for (int j = 0; j < TN; j++) acc[i][j] = 0.f;

    for (int k0 = 0; k0 < K; k0 += BK) {
        // Load A tile (transpose into As[k][m])
        float4 av = *(const float4*)&A[(long long)(row0 + arow) * K + k0 + ak];
        As[ak + 0][arow] = av.x;
        As[ak + 1][arow] = av.y;
        As[ak + 2][arow] = av.z;
        As[ak + 3][arow] = av.w;

        if (TRANS_B) {
            // B is [N,K] row-major -> Bs[k][n]
            float4 bv = *(const float4*)&B[(long long)(col0 + arow) * K + k0 + ak];
            Bs[ak + 0][arow] = bv.x;
            Bs[ak + 1][arow] = bv.y;
            Bs[ak + 2][arow] = bv.z;
            Bs[ak + 3][arow] = bv.w;
        } else {
            // B is [K,N] row-major -> Bs[k][n] direct
            float4 bv = *(const float4*)&B[(long long)(k0 + bkr) * N + col0 + bn4];
            *(float4*)&Bs[bkr][bn4] = bv;
        }
        __syncthreads();

#pragma unroll
        for (int k = 0; k < BK; k++) {
            float ra[TM], rb[TN];
#pragma unroll
            for (int i = 0; i < TM; i++) ra[i] = As[k][ty * TM + i];
#pragma unroll
            for (int j = 0; j < TN; j++) rb[j] = Bs[k][tx * TN + j];
#pragma unroll
            for (int i = 0; i < TM; i++)
#pragma unroll
                for (int j = 0; j < TN; j++) acc[i][j] = fmaf(ra[i], rb[j], acc[i][j]);
        }
        __syncthreads();
    }

#pragma unroll
    for (int i = 0; i < TM; i++) {
        const int m = row0 + ty * TM + i;
#pragma unroll
        for (int j = 0; j < TN; j += 4) {
            const int n = col0 + tx * TN + j;
            float4 o;
            o.x = acc[i][j + 0] * alpha;
            o.y = acc[i][j + 1] * alpha;
            o.z = acc[i][j + 2] * alpha;
            o.w = acc[i][j + 3] * alpha;
            if (HAS_BIAS) {
                o.x += bias[n + 0];
                o.y += bias[n + 1];
                o.z += bias[n + 2];
                o.w += bias[n + 3];
            }
            *(float4*)&C[(long long)m * N + n] = o;
        }
    }
}

// ---------------------------------------------------------------------------
// Row softmax over SEQ=2048 columns, one block (256 threads) per row.
// Each thread keeps 8 elements in registers: single gmem read + write.
// ---------------------------------------------------------------------------
__global__ void __launch_bounds__(256) softmax_kernel(float* __restrict__ S)
{
    const long long row = blockIdx.x;
    float* p = S + row * (long long)SEQ;
    const int tid = threadIdx.x;

    float4 v0 = *(float4*)&p[tid * 4];
    float4 v1 = *(float4*)&p[1024 + tid * 4];

    float m = fmaxf(fmaxf(fmaxf(v0.x, v0.y), fmaxf(v0.z, v0.w)),
                    fmaxf(fmaxf(v1.x, v1.y), fmaxf(v1.z, v1.w)));

    __shared__ float sh[8];
#pragma unroll
    for (int o = 16; o; o >>= 1) m = fmaxf(m, __shfl_xor_sync(0xffffffffu, m, o));
    if ((tid & 31) == 0) sh[tid >> 5] = m;
    __syncthreads();
    m = sh[0];
#pragma unroll
    for (int i = 1; i < 8; i++) m = fmaxf(m, sh[i]);
    __syncthreads();

    v0.x = __expf(v0.x - m); v0.y = __expf(v0.y - m);
    v0.z = __expf(v0.z - m); v0.w = __expf(v0.w - m);
    v1.x = __expf(v1.x - m); v1.y = __expf(v1.y - m);
    v1.z = __expf(v1.z - m); v1.w = __expf(v1.w - m);

    float s = (v0.x + v0.y + v0.z + v0.w) + (v1.x + v1.y + v1.z + v1.w);
#pragma unroll
    for (int o = 16; o; o >>= 1) s += __shfl_xor_sync(0xffffffffu, s, o);
    if ((tid & 31) == 0) sh[tid >> 5] = s;
    __syncthreads();
    s = 0.f;
#pragma unroll
    for (int i = 0; i < 8; i++) s += sh[i];

    const float inv = 1.f / s;
    v0.x *= inv; v0.y *= inv; v0.z *= inv; v0.w *= inv;
    v1.x *= inv; v1.y *= inv; v1.z *= inv; v1.w *= inv;

    *(float4*)&p[tid * 4]        = v0;
    *(float4*)&p[1024 + tid * 4] = v1;
}

// ---------------------------------------------------------------------------
extern "C" void kernel_launch(void* const* d_in, const int* in_sizes, int n_in,
                              void* d_out, int out_size)
{
    const float* x  = (const float*)d_in[0];
    const float* Wq = (const float*)d_in[1];
    const float* bq = (const float*)d_in[2];
    const float* Wk = (const float*)d_in[3];
    const float* bk = (const float*)d_in[4];
    const float* Wv = (const float*)d_in[5];
    const float* bv = (const float*)d_in[6];
    const float* Wo = (const float*)d_in[7];
    const float* bo = (const float*)d_in[8];
    float* out = (float*)d_out;

    float *Q, *K, *V, *S, *A;
    cudaGetSymbolAddress((void**)&Q, g_Q);
    cudaGetSymbolAddress((void**)&K, g_K);
    cudaGetSymbolAddress((void**)&V, g_V);
    cudaGetSymbolAddress((void**)&S, g_S);
    cudaGetSymbolAddress((void**)&A, g_A);

    const dim3 blk(256);

    // QKV projections: [8192,1024] = x[8192,1024] @ W^T + b
    const dim3 gproj(DM / BN, TOK / BM, 1);
    gemm_kernel<true, true><<<gproj, blk>>>(x, Wq, bq, Q, TOK, DM, DM, 1.f, 0, 0, 0);
    gemm_kernel<true, true><<<gproj, blk>>>(x, Wk, bk, K, TOK, DM, DM, 1.f, 0, 0, 0);
    gemm_kernel<true, true><<<gproj, blk>>>(x, Wv, bv, V, TOK, DM, DM, 1.f, 0, 0, 0);

    // scores: per batch [2048,2048] = Q K^T * 0.125
    const dim3 gscore(SEQ / BN, SEQ / BM, NB);
    gemm_kernel<true, false><<<gscore, blk>>>(
        Q, K, nullptr, S, SEQ, SEQ, DM, 0.125f,
        (long long)SEQ * DM, (long long)SEQ * DM, (long long)SEQ * SEQ);

    // softmax over rows
    softmax_kernel<<<TOK, blk>>>(S);

    // attn @ V: per batch [2048,1024]
    const dim3 gav(DM / BN, SEQ / BM, NB);
    gemm_kernel<false, false><<<gav, blk>>>(
        S, V, nullptr, A, SEQ, DM, SEQ, 1.f,
        (long long)SEQ * SEQ, (long long)SEQ * DM, (long long)SEQ * DM);

    // output projection
    gemm_kernel<true, true><<<gproj, blk>>>(A, Wo, bo, out, TOK, DM, DM, 1.f, 0, 0, 0);
}

// round 4
// speedup vs baseline: 2.1053x; 2.1053x over previous
#include <cuda_runtime.h>
#include <cstdint>

// ---------------------------------------------------------------------------
// FourierAttention via warp-level mma.sync (HMMA, plain sm_80+ PTX — the
// harness targets sm_103 without the 'a' suffix, so tcgen05 is unavailable).
// All 5 GEMMs: C[m,n] = alpha * sum_k A[m,k]*B[n,k] (+bias), fp32 in/out.
// fp32 emulated as bf16 split-3: a=hi+lo; a*b ~= hi*hi + hi*lo + lo*hi.
// Tile: 128x128, BK=32 fp32, 8 warps (64x32 each), double-buffered SMEM.
// ---------------------------------------------------------------------------

#define SEQ 2048
#define DM  1024
#define NB  4
#define TOK (NB * SEQ)

__device__ float g_Q [(long long)TOK * DM];
__device__ float g_K [(long long)TOK * DM];
__device__ float g_V [(long long)TOK * DM];
__device__ float g_VT[(long long)TOK * DM];
__device__ float g_S [(long long)NB * SEQ * SEQ];
__device__ float g_A [(long long)TOK * DM];

// ---------------- helpers ----------------
__device__ __forceinline__ uint32_t pk_bf16x2(float lo, float hi) {
    uint32_t r;
    asm("cvt.rn.bf16x2.f32 %0, %1, %2;" : "=r"(r) : "f"(hi), "f"(lo));
    return r;
}
__device__ __forceinline__ void mma_bf16(float* d, const uint32_t* a,
                                         const uint32_t* b) {
    asm volatile(
        "mma.sync.aligned.m16n8k16.row.col.f32.bf16.bf16.f32 "
        "{%0,%1,%2,%3}, {%4,%5,%6,%7}, {%8,%9}, {%0,%1,%2,%3};"
        : "+f"(d[0]), "+f"(d[1]), "+f"(d[2]), "+f"(d[3])
        : "r"(a[0]), "r"(a[1]), "r"(a[2]), "r"(a[3]), "r"(b[0]), "r"(b[1]));
}

// convert 16 fp32 (4 float4) -> 16 hi bf16 + 16 lo bf16, store 2x16B each
__device__ __forceinline__ void cvt16(const float4* s, uint16_t* dh, uint16_t* dl) {
    uint32_t h[8], l[8];
#pragma unroll
    for (int q = 0; q < 4; q++) {
        float4 u = s[q];
        uint32_t h0 = pk_bf16x2(u.x, u.y);
        uint32_t h1 = pk_bf16x2(u.z, u.w);
        float r0 = u.x - __uint_as_float(h0 << 16);
        float r1 = u.y - __uint_as_float(h0 & 0xffff0000u);
        float r2 = u.z - __uint_as_float(h1 << 16);
        float r3 = u.w - __uint_as_float(h1 & 0xffff0000u);
        h[q * 2]     = h0;
        h[q * 2 + 1] = h1;
        l[q * 2]     = pk_bf16x2(r0, r1);
        l[q * 2 + 1] = pk_bf16x2(r2, r3);
    }
    *(uint4*)dh       = make_uint4(h[0], h[1], h[2], h[3]);
    *(uint4*)(dh + 8) = make_uint4(h[4], h[5], h[6], h[7]);
    *(uint4*)dl       = make_uint4(l[0], l[1], l[2], l[3]);
    *(uint4*)(dl + 8) = make_uint4(l[4], l[5], l[6], l[7]);
}

// ---------------- GEMM ----------------
#define BM 128
#define BN 128
#define BKF 32                      // fp32 k-elems per chunk
#define LDSS 40                     // smem row stride in bf16 elems (pad -> conflict-free)
#define TILE_U16 (128 * LDSS)       // 5120
#define BUF_U16  (4 * TILE_U16)     // Ah|Al|Bh|Bl
#define SMEM_BYTES (2 * BUF_U16 * 2)  // 81920

template <bool HAS_BIAS>
__global__ void __launch_bounds__(256) mma_gemm(
    const float* __restrict__ A, const float* __restrict__ B,
    const float* __restrict__ bias, float* __restrict__ C,
    int N, int K, float alpha,
    long long sA, long long sB, long long sC)
{
    extern __shared__ uint16_t sm[];
    const int tid  = threadIdx.x;
    const int lane = tid & 31;
    const int wid  = tid >> 5;
    const int warpM = wid >> 2;      // 0..1
    const int warpN = wid & 3;       // 0..3
    const int g  = lane >> 2;        // 0..7
    const int tg = lane & 3;         // 0..3

    const long long z = blockIdx.z;
    const float* Ab = A + z * sA + (long long)blockIdx.y * BM * K;
    const float* Bb = B + z * sB + (long long)blockIdx.x * BN * K;

    const int arow = tid >> 1;           // 0..127
    const int acol = (tid & 1) * 16;     // 0 / 16

    float acc[4][4][4];
#pragma unroll
    for (int i = 0; i < 4; i++)
#pragma unroll
        for (int j = 0; j < 4; j++)
#pragma unroll
            for (int r = 0; r < 4; r++) acc[i][j][r] = 0.f;

    float4 sa[4], sb[4];
    // prologue: chunk 0
    {
        const float4* pA = (const float4*)(Ab + (long long)arow * K + acol);
        const float4* pB = (const float4*)(Bb + (long long)arow * K + acol);
#pragma unroll
        for (int j = 0; j < 4; j++) { sa[j] = pA[j]; sb[j] = pB[j]; }
        uint16_t* Ah = sm;
        cvt16(sa, &Ah[arow * LDSS + acol], &Ah[TILE_U16 + arow * LDSS + acol]);
        cvt16(sb, &Ah[2 * TILE_U16 + arow * LDSS + acol],
                  &Ah[3 * TILE_U16 + arow * LDSS + acol]);
    }
    __syncthreads();

    const int nc = K / BKF;
    for (int c = 0; c < nc; c++) {
        const uint16_t* Ah = sm + (c & 1) * BUF_U16;
        const uint16_t* Al = Ah + TILE_U16;
        const uint16_t* Bh = Ah + 2 * TILE_U16;
        const uint16_t* Bl = Ah + 3 * TILE_U16;

        if (c + 1 < nc) {
            const long long kb = (long long)(c + 1) * BKF;
            const float4* pA = (const float4*)(Ab + (long long)arow * K + kb + acol);
            const float4* pB = (const float4*)(Bb + (long long)arow * K + kb + acol);
#pragma unroll
            for (int j = 0; j < 4; j++) { sa[j] = pA[j]; sb[j] = pB[j]; }
        }

#pragma unroll
        for (int ks = 0; ks < 2; ks++) {
            const int kk = ks * 16 + tg * 2;
            uint32_t ah[4][4], al[4][4], bh[4][2], bl[4][2];
#pragma unroll
            for (int mt = 0; mt < 4; mt++) {
                const int ro = (warpM * 64 + mt * 16 + g) * LDSS + kk;
                ah[mt][0] = *(const uint32_t*)&Ah[ro];
                ah[mt][1] = *(const uint32_t*)&Ah[ro + 8 * LDSS];
                ah[mt][2] = *(const uint32_t*)&Ah[ro + 8];
                ah[mt][3] = *(const uint32_t*)&Ah[ro + 8 * LDSS + 8];
                al[mt][0] = *(const uint32_t*)&Al[ro];
                al[mt][1] = *(const uint32_t*)&Al[ro + 8 * LDSS];
                al[mt][2] = *(const uint32_t*)&Al[ro + 8];
                al[mt][3] = *(const uint32_t*)&Al[ro + 8 * LDSS + 8];
            }
#pragma unroll
            for (int nt = 0; nt < 4; nt++) {
                const int qo = (warpN * 32 + nt * 8 + g) * LDSS + kk;
                bh[nt][0] = *(const uint32_t*)&Bh[qo];
                bh[nt][1] = *(const uint32_t*)&Bh[qo + 8];
                bl[nt][0] = *(const uint32_t*)&Bl[qo];
                bl[nt][1] = *(const uint32_t*)&Bl[qo + 8];
            }
#pragma unroll
            for (int mt = 0; mt < 4; mt++)
#pragma unroll
                for (int nt = 0; nt < 4; nt++) {
                    mma_bf16(acc[mt][nt], ah[mt], bh[nt]);
                    mma_bf16(acc[mt][nt], ah[mt], bl[nt]);
                    mma_bf16(acc[mt][nt], al[mt], bh[nt]);
                }
        }

        if (c + 1 < nc) {
            uint16_t* Wh = sm + ((c + 1) & 1) * BUF_U16;
            cvt16(sa, &Wh[arow * LDSS + acol], &Wh[TILE_U16 + arow * LDSS + acol]);
            cvt16(sb, &Wh[2 * TILE_U16 + arow * LDSS + acol],
                      &Wh[3 * TILE_U16 + arow * LDSS + acol]);
        }
        __syncthreads();
    }

    // epilogue
    const int mbase = blockIdx.y * BM + warpM * 64;
    const int nbase = blockIdx.x * BN + warpN * 32;
    float* Cz = C + z * sC;
#pragma unroll
    for (int mt = 0; mt < 4; mt++) {
        const int m = mbase + mt * 16 + g;
#pragma unroll
        for (int nt = 0; nt < 4; nt++) {
            const int n = nbase + nt * 8 + tg * 2;
            float b0 = 0.f, b1 = 0.f;
            if (HAS_BIAS) { b0 = bias[n]; b1 = bias[n + 1]; }
            float2 v0, v1;
            v0.x = acc[mt][nt][0] * alpha + b0;
            v0.y = acc[mt][nt][1] * alpha + b1;
            v1.x = acc[mt][nt][2] * alpha + b0;
            v1.y = acc[mt][nt][3] * alpha + b1;
            *(float2*)&Cz[(long long)m * N + n]       = v0;
            *(float2*)&Cz[(long long)(m + 8) * N + n] = v1;
        }
    }
}

// ---------------- softmax (rows of 2048) ----------------
__global__ void __launch_bounds__(256) softmax_kernel(float* __restrict__ S)
{
    const long long row = blockIdx.x;
    float* p = S + row * (long long)SEQ;
    const int tid = threadIdx.x;

    float4 v0 = *(float4*)&p[tid * 4];
    float4 v1 = *(float4*)&p[1024 + tid * 4];

    float m = fmaxf(fmaxf(fmaxf(v0.x, v0.y), fmaxf(v0.z, v0.w)),
                    fmaxf(fmaxf(v1.x, v1.y), fmaxf(v1.z, v1.w)));
    __shared__ float sh[8];
#pragma unroll
    for (int o = 16; o; o >>= 1) m = fmaxf(m, __shfl_xor_sync(0xffffffffu, m, o));
    if ((tid & 31) == 0) sh[tid >> 5] = m;
    __syncthreads();
    m = sh[0];
#pragma unroll
    for (int i = 1; i < 8; i++) m = fmaxf(m, sh[i]);
    __syncthreads();

    v0.x = __expf(v0.x - m); v0.y = __expf(v0.y - m);
    v0.z = __expf(v0.z - m); v0.w = __expf(v0.w - m);
    v1.x = __expf(v1.x - m); v1.y = __expf(v1.y - m);
    v1.z = __expf(v1.z - m); v1.w = __expf(v1.w - m);

    float s = (v0.x + v0.y + v0.z + v0.w) + (v1.x + v1.y + v1.z + v1.w);
#pragma unroll
    for (int o = 16; o; o >>= 1) s += __shfl_xor_sync(0xffffffffu, s, o);
    if ((tid & 31) == 0) sh[tid >> 5] = s;
    __syncthreads();
    s = 0.f;
#pragma unroll
    for (int i = 0; i < 8; i++) s += sh[i];

    const float inv = 1.f / s;
    v0.x *= inv; v0.y *= inv; v0.z *= inv; v0.w *= inv;
    v1.x *= inv; v1.y *= inv; v1.z *= inv; v1.w *= inv;
    *(float4*)&p[tid * 4] = v0;
    *(float4*)&p[1024 + tid * 4] = v1;
}

// ---------------- V transpose (per batch [SEQ,DM] -> [DM,SEQ]) ----------------
__global__ void __launch_bounds__(256) transpose_kernel(
    const float* __restrict__ V, float* __restrict__ VT)
{
    __shared__ float t[32][33];
    const long long z = blockIdx.z;
    const float* Vb = V + z * (long long)SEQ * DM;
    float* VTb = VT + z * (long long)DM * SEQ;
    const int d0 = blockIdx.x * 32;
    const int s0 = blockIdx.y * 32;
    const int tx = threadIdx.x, ty = threadIdx.y;
#pragma unroll
    for (int i = 0; i < 32; i += 8)
        t[ty + i][tx] = Vb[(long long)(s0 + ty + i) * DM + d0 + tx];
    __syncthreads();
#pragma unroll
    for (int i = 0; i < 32; i += 8)
        VTb[(long long)(d0 + ty + i) * SEQ + s0 + tx] = t[tx][ty + i];
}

// ---------------- host ----------------
extern "C" void kernel_launch(void* const* d_in, const int* in_sizes, int n_in,
                              void* d_out, int out_size)
{
    const float* x  = (const float*)d_in[0];
    const float* Wq = (const float*)d_in[1];
    const float* bq = (const float*)d_in[2];
    const float* Wk = (const float*)d_in[3];
    const float* bk = (const float*)d_in[4];
    const float* Wv = (const float*)d_in[5];
    const float* bv = (const float*)d_in[6];
    const float* Wo = (const float*)d_in[7];
    const float* bo = (const float*)d_in[8];
    float* out = (float*)d_out;

    float *Q, *Kp, *V, *VT, *S, *Ao;
    cudaGetSymbolAddress((void**)&Q,  g_Q);
    cudaGetSymbolAddress((void**)&Kp, g_K);
    cudaGetSymbolAddress((void**)&V,  g_V);
    cudaGetSymbolAddress((void**)&VT, g_VT);
    cudaGetSymbolAddress((void**)&S,  g_S);
    cudaGetSymbolAddress((void**)&Ao, g_A);

    cudaFuncSetAttribute(mma_gemm<true>,
                         cudaFuncAttributeMaxDynamicSharedMemorySize, SMEM_BYTES);
    cudaFuncSetAttribute(mma_gemm<false>,
                         cudaFuncAttributeMaxDynamicSharedMemorySize, SMEM_BYTES);

    const dim3 blk(256);
    const dim3 gproj(DM / BN, TOK / BM, 1);          // (8, 64)
    const dim3 gscore(SEQ / BN, SEQ / BM, NB);       // (16, 16, 4)
    const dim3 gav(DM / BN, SEQ / BM, NB);           // (8, 16, 4)

    mma_gemm<true><<<gproj, blk, SMEM_BYTES>>>(x, Wq, bq, Q,  DM, DM, 1.f, 0, 0, 0);
    mma_gemm<true><<<gproj, blk, SMEM_BYTES>>>(x, Wk, bk, Kp, DM, DM, 1.f, 0, 0, 0);
    mma_gemm<true><<<gproj, blk, SMEM_BYTES>>>(x, Wv, bv, V,  DM, DM, 1.f, 0, 0, 0);

    transpose_kernel<<<dim3(DM / 32, SEQ / 32, NB), dim3(32, 8)>>>(V, VT);

    mma_gemm<false><<<gscore, blk, SMEM_BYTES>>>(
        Q, Kp, nullptr, S, SEQ, DM, 0.125f,
        (long long)SEQ * DM, (long long)SEQ * DM, (long long)SEQ * SEQ);

    softmax_kernel<<<TOK, blk>>>(S);

    mma_gemm<false><<<gav, blk, SMEM_BYTES>>>(
        S, VT, nullptr, Ao, DM, SEQ, 1.f,
        (long long)SEQ * SEQ, (long long)DM * SEQ, (long long)SEQ * DM);

    mma_gemm<true><<<gproj, blk, SMEM_BYTES>>>(Ao, Wo, bo, out, DM, DM, 1.f, 0, 0, 0);
}